// round 9
// baseline (speedup 1.0000x reference)
#include <cuda_runtime.h>
#include <math.h>
#include <stdint.h>

// ---------------------------------------------------------------------------
// Shapes (fixed by the problem)
// ---------------------------------------------------------------------------
#define B    32
#define L    65536
#define LOUT 64536          // L - 1000 (slice [500:-500])

// Scratch (device globals; allocation in kernel_launch is forbidden)
__device__ float g_y[(size_t)B * 40 * L];   // motif output (post-softplus)
__device__ float g_s[(size_t)B * 4 * L];    // reduce output
__device__ float g_t[(size_t)B * 4 * L];    // fftconv output
__device__ float g_m[(size_t)B * 40 * L];   // motifact (gated)

// ---------------------------------------------------------------------------
// Kernel 1: motif conv (4->40, K=51, pad 25) + softplus + reduce (40->4, 1x1)
//   (proven scalar version — frozen)
// ---------------------------------------------------------------------------
#define T1   512
#define TH1  128
#define K1P  52
#define XW1  564

__global__ __launch_bounds__(TH1)
void motif_kernel(const float* __restrict__ x,
                  const float* __restrict__ wm, const float* __restrict__ bm,
                  const float* __restrict__ wr, const float* __restrict__ br)
{
    __shared__ __align__(16) float swm[4 * K1P * 40];
    __shared__ float swr[4 * 40];
    __shared__ float sbm[40];
    __shared__ float sbr[4];
    __shared__ __align__(16) float sx[4 * XW1];

    const int b   = blockIdx.y;
    const int l0  = blockIdx.x * T1;
    const int tid = threadIdx.x;

    for (int i = tid; i < 4 * K1P * 40; i += TH1) {
        int c  = i / (K1P * 40);
        int r  = i - c * (K1P * 40);
        int k  = r / 40;
        int oc = r - k * 40;
        swm[i] = (k < 51) ? wm[(oc * 4 + c) * 51 + k] : 0.f;
    }
    for (int i = tid; i < 160; i += TH1) swr[i] = wr[i];
    if (tid < 40) sbm[tid] = bm[tid];
    if (tid < 4)  sbr[tid] = br[tid];

    for (int i = tid; i < 4 * XW1; i += TH1) {
        int c   = i / XW1;
        int off = i - c * XW1;
        int g   = l0 - 25 + off;
        sx[i]   = (g >= 0 && g < L) ? x[(b * 4 + c) * L + g] : 0.f;
    }
    __syncthreads();

    const int tp = tid * 4;

    float sacc[4][4];
#pragma unroll
    for (int rc = 0; rc < 4; rc++) {
        float bv = sbr[rc];
#pragma unroll
        for (int j = 0; j < 4; j++) sacc[rc][j] = bv;
    }

    for (int ocg = 0; ocg < 40; ocg += 8) {
        float acc[8][4];
#pragma unroll
        for (int o = 0; o < 8; o++) {
            float bv = sbm[ocg + o];
#pragma unroll
            for (int j = 0; j < 4; j++) acc[o][j] = bv;
        }

#pragma unroll
        for (int c = 0; c < 4; c++) {
            const float* xb = &sx[c * XW1 + tp];
            const float* wb = &swm[c * (K1P * 40) + ocg];
#pragma unroll 1
            for (int kg = 0; kg < K1P / 4; kg++) {
                const int k0 = kg * 4;
                float xq[8];
                float4 xa = *(const float4*)(xb + k0);
                float4 xc = *(const float4*)(xb + k0 + 4);
                xq[0]=xa.x; xq[1]=xa.y; xq[2]=xa.z; xq[3]=xa.w;
                xq[4]=xc.x; xq[5]=xc.y; xq[6]=xc.z; xq[7]=xc.w;
#pragma unroll
                for (int kk = 0; kk < 4; kk++) {
                    float4 wa = *(const float4*)(wb + (k0 + kk) * 40);
                    float4 wc = *(const float4*)(wb + (k0 + kk) * 40 + 4);
                    float wv[8] = {wa.x, wa.y, wa.z, wa.w, wc.x, wc.y, wc.z, wc.w};
#pragma unroll
                    for (int j = 0; j < 4; j++) {
                        float xv = xq[kk + j];
#pragma unroll
                        for (int o = 0; o < 8; o++)
                            acc[o][j] = fmaf(wv[o], xv, acc[o][j]);
                    }
                }
            }
        }

#pragma unroll
        for (int o = 0; o < 8; o++) {
            const int oc = ocg + o;
            float4 yv;
            float* yp = (float*)&yv;
#pragma unroll
            for (int j = 0; j < 4; j++) {
                float v  = acc[o][j];
                float sp = fmaxf(v, 0.f) + __logf(1.f + __expf(-fabsf(v)));
                yp[j] = sp;
#pragma unroll
                for (int rc = 0; rc < 4; rc++)
                    sacc[rc][j] = fmaf(swr[rc * 40 + oc], sp, sacc[rc][j]);
            }
            *(float4*)&g_y[(size_t)(b * 40 + oc) * L + l0 + tp] = yv;
        }
    }

#pragma unroll
    for (int rc = 0; rc < 4; rc++) {
        float4 sv = make_float4(sacc[rc][0], sacc[rc][1], sacc[rc][2], sacc[rc][3]);
        *(float4*)&g_s[(size_t)(b * 4 + rc) * L + l0 + tp] = sv;
    }
}

// ---------------------------------------------------------------------------
// Kernel 2: fftconv (4->4, K=401, pad 200)   (frozen)
// ---------------------------------------------------------------------------
#define T3   512
#define TH3  128
#define K3P  404
#define XW3  920

__global__ __launch_bounds__(TH3)
void fftconv_kernel(const float* __restrict__ wf, const float* __restrict__ bf)
{
    __shared__ __align__(16) float sw[4 * K3P * 4];
    __shared__ float sb[4];
    __shared__ __align__(16) float ss[4 * XW3];

    const int b   = blockIdx.y;
    const int l0  = blockIdx.x * T3;
    const int tid = threadIdx.x;

    for (int i = tid; i < 4 * K3P * 4; i += TH3) {
        int c  = i / (K3P * 4);
        int r  = i - c * (K3P * 4);
        int k  = r / 4;
        int oc = r - k * 4;
        sw[i] = (k < 401) ? wf[(oc * 4 + c) * 401 + k] : 0.f;
    }
    if (tid < 4) sb[tid] = bf[tid];

    for (int i = tid; i < 4 * XW3; i += TH3) {
        int c   = i / XW3;
        int off = i - c * XW3;
        int g   = l0 - 200 + off;
        ss[i]   = (g >= 0 && g < L) ? g_s[(size_t)(b * 4 + c) * L + g] : 0.f;
    }
    __syncthreads();

    const int tp = tid * 4;
    float acc[4][4];
#pragma unroll
    for (int oc = 0; oc < 4; oc++) {
        float bv = sb[oc];
#pragma unroll
        for (int j = 0; j < 4; j++) acc[oc][j] = bv;
    }

#pragma unroll
    for (int c = 0; c < 4; c++) {
        const float* xb = &ss[c * XW3 + tp];
        const float* wb = &sw[c * (K3P * 4)];
#pragma unroll 1
        for (int kg = 0; kg < K3P / 4; kg++) {
            const int k0 = kg * 4;
            float xq[8];
            float4 xa = *(const float4*)(xb + k0);
            float4 xc = *(const float4*)(xb + k0 + 4);
            xq[0]=xa.x; xq[1]=xa.y; xq[2]=xa.z; xq[3]=xa.w;
            xq[4]=xc.x; xq[5]=xc.y; xq[6]=xc.z; xq[7]=xc.w;
#pragma unroll
            for (int kk = 0; kk < 4; kk++) {
                float4 wv = *(const float4*)(wb + (k0 + kk) * 4);
                float w0 = wv.x, w1 = wv.y, w2 = wv.z, w3 = wv.w;
#pragma unroll
                for (int j = 0; j < 4; j++) {
                    float xv = xq[kk + j];
                    acc[0][j] = fmaf(w0, xv, acc[0][j]);
                    acc[1][j] = fmaf(w1, xv, acc[1][j]);
                    acc[2][j] = fmaf(w2, xv, acc[2][j]);
                    acc[3][j] = fmaf(w3, xv, acc[3][j]);
                }
            }
        }
    }

#pragma unroll
    for (int oc = 0; oc < 4; oc++) {
        float4 tv = make_float4(acc[oc][0], acc[oc][1], acc[oc][2], acc[oc][3]);
        *(float4*)&g_t[(size_t)(b * 4 + oc) * L + l0 + tp] = tv;
    }
}

// ---------------------------------------------------------------------------
// Kernel 3: expand (4->40, 1x1) + sigmoid gate * y  -> motifact  (frozen)
// ---------------------------------------------------------------------------
__global__ __launch_bounds__(256)
void gate_kernel(const float* __restrict__ we, const float* __restrict__ be)
{
    __shared__ float sw[160];
    __shared__ float sb[40];
    const int tid = threadIdx.x;
    if (tid < 160) sw[tid] = we[tid];
    if (tid < 40)  sb[tid] = be[tid];
    __syncthreads();

    const int b = blockIdx.y;
    const int l = (blockIdx.x * 256 + tid) * 4;

    float4 tv[4];
#pragma unroll
    for (int rc = 0; rc < 4; rc++)
        tv[rc] = *(const float4*)&g_t[(size_t)(b * 4 + rc) * L + l];

    for (int oc = 0; oc < 40; oc++) {
        float w0 = sw[oc * 4 + 0], w1 = sw[oc * 4 + 1];
        float w2 = sw[oc * 4 + 2], w3 = sw[oc * 4 + 3];
        float bb = sb[oc];
        float4 g;
        g.x = bb + w0 * tv[0].x + w1 * tv[1].x + w2 * tv[2].x + w3 * tv[3].x;
        g.y = bb + w0 * tv[0].y + w1 * tv[1].y + w2 * tv[2].y + w3 * tv[3].y;
        g.z = bb + w0 * tv[0].z + w1 * tv[1].z + w2 * tv[2].z + w3 * tv[3].z;
        g.w = bb + w0 * tv[0].w + w1 * tv[1].w + w2 * tv[2].w + w3 * tv[3].w;
        g.x = 1.f / (1.f + __expf(-g.x));
        g.y = 1.f / (1.f + __expf(-g.y));
        g.z = 1.f / (1.f + __expf(-g.z));
        g.w = 1.f / (1.f + __expf(-g.w));
        size_t idx = (size_t)(b * 40 + oc) * L + l;
        float4 yv = *(const float4*)&g_y[idx];
        float4 mv = make_float4(g.x * yv.x, g.y * yv.y, g.z * yv.z, g.w * yv.w);
        *(float4*)&g_m[idx] = mv;
    }
}

// ---------------------------------------------------------------------------
// Kernel 4: effect conv (40->2, K=601) via tf32 mma, oc-packed M mapping.
//
//   Tile = 64 positions. M = 16 rows = [oc0 x 8 pos-groups ; oc1 x 8].
//   A[oc*8+mp][j] = w_oc[j - 8*mp]  (same k-index for both oc at a row pair)
//     -> weights stored uint2 {w0[i], w1[i]}: full A frag = 2 x LDS.64.
//   B[j][n] = xm[TO + 200 + J0 + j + n]; b1 index = b0 + 4
//     -> x window stored uint2 {x[i], x[i+4]}: B frag = 1 x LDS.64.
//   j in [0, 664) (601 + 56 band, 90.5% efficiency), 83 chunks.
//   Warp: 16 tiles (1024 pos). CTA: 4 warps = 4096 pos. 1 channel per chunk.
// ---------------------------------------------------------------------------
#define ET_POS   4096       // positions per CTA
#define ET_TH    128
#define ET_NT    16         // 64-pos tiles per warp
#define ET_NJ    664        // extended j range (83 chunks of 8)
#define ET_WPAD  800        // weight band entries: 128 + 657 + guard
#define ET_XW    4704       // x window entries: 4096-64+664+... pad

__device__ __forceinline__ uint32_t f2tf(float v) {
    uint32_t r;
    asm("cvt.rna.tf32.f32 %0, %1;" : "=r"(r) : "f"(v));
    return r;
}

__device__ __forceinline__ void mma_tf32(float& d0, float& d1, float& d2, float& d3,
                                         uint32_t a0, uint32_t a1, uint32_t a2, uint32_t a3,
                                         uint32_t b0, uint32_t b1) {
    asm volatile(
        "mma.sync.aligned.m16n8k8.row.col.f32.tf32.tf32.f32 "
        "{%0,%1,%2,%3}, {%4,%5,%6,%7}, {%8,%9}, {%0,%1,%2,%3};\n"
        : "+f"(d0), "+f"(d1), "+f"(d2), "+f"(d3)
        : "r"(a0), "r"(a1), "r"(a2), "r"(a3), "r"(b0), "r"(b1));
}

__global__ __launch_bounds__(ET_TH)
void effect_kernel(const float* __restrict__ w, const float* __restrict__ bias,
                   float* __restrict__ out)
{
    __shared__ __align__(16) uint2 sm_x[ET_XW];    // {tf32(x[i]), tf32(x[i+4])}
    __shared__ __align__(16) uint2 sm_w[ET_WPAD];  // {tf32(w0[k]), tf32(w1[k])}

    const int b    = blockIdx.y;
    const int LOc  = blockIdx.x * ET_POS;          // CTA base in output coords
    const int tid  = threadIdx.x;
    const int wid  = tid >> 5;
    const int lane = tid & 31;
    const int grp  = lane >> 2;                    // groupID (0..7)
    const int tig  = lane & 3;                     // threadID_in_group (0..3)
    const int wrel = wid * (ET_NT * 64);           // warp base rel CTA

    // acc[t]: c0,c1 = oc0 @ pos (8g+2t, +1); c2,c3 = oc1 @ same pos
    float acc[ET_NT][4];
    const float b0v = bias[0], b1v = bias[1];
#pragma unroll
    for (int t = 0; t < ET_NT; t++) {
        acc[t][0] = b0v; acc[t][1] = b0v;
        acc[t][2] = b1v; acc[t][3] = b1v;
    }

#pragma unroll 1
    for (int ch = 0; ch < 40; ch++) {
        __syncthreads();   // protect previous chunk
        // weights: band at offset 128, oc-paired, tf32-converted
        for (int i = tid; i < ET_WPAD; i += ET_TH) {
            int k = i - 128;
            float v0 = 0.f, v1 = 0.f;
            if (k >= 0 && k < 601) {
                v0 = w[((size_t)(0 * 40 + ch)) * 601 + k];
                v1 = w[((size_t)(1 * 40 + ch)) * 601 + k];
            }
            sm_w[i] = make_uint2(f2tf(v0), f2tf(v1));
        }
        // x window: {x[g], x[g+4]}, g = LOc + 200 + i
        {
            const float* xm = &g_m[(size_t)(b * 40 + ch) * L];
            for (int i = tid; i < ET_XW; i += ET_TH) {
                int g  = LOc + 200 + i;
                float v0 = (g < L)     ? xm[g]     : 0.f;
                float v1 = (g + 4 < L) ? xm[g + 4] : 0.f;
                sm_x[i] = make_uint2(f2tf(v0), f2tf(v1));
            }
        }
        __syncthreads();

        const uint2* xw = &sm_x[wrel];
        int ai = 128 + tig - 8 * grp;   // + J0 each step
        int bi = grp + tig;             // + J0 each step (+ t*64)
#pragma unroll 1
        for (int J0 = 0; J0 < ET_NJ; J0 += 8) {
            uint2 aA = sm_w[ai];        // (a0, a1) = (w0[k], w1[k])
            uint2 aB = sm_w[ai + 4];    // (a2, a3)
#pragma unroll
            for (int t = 0; t < ET_NT; t++) {
                uint2 bb = xw[bi + t * 64];
                mma_tf32(acc[t][0], acc[t][1], acc[t][2], acc[t][3],
                         aA.x, aA.y, aB.x, aB.y, bb.x, bb.y);
            }
            ai += 8; bi += 8;
        }
    }

    // epilogue: sigmoid + store
    float* o0 = out + (size_t)(b * 2 + 0) * LOUT;
    float* o1 = out + (size_t)(b * 2 + 1) * LOUT;
#pragma unroll
    for (int t = 0; t < ET_NT; t++) {
        int p = LOc + wrel + t * 64 + 8 * grp + 2 * tig;
        float s0 = 1.f / (1.f + __expf(-acc[t][0]));
        float s1 = 1.f / (1.f + __expf(-acc[t][1]));
        float s2 = 1.f / (1.f + __expf(-acc[t][2]));
        float s3 = 1.f / (1.f + __expf(-acc[t][3]));
        if (p < LOUT)     { o0[p]     = s0; o1[p]     = s2; }
        if (p + 1 < LOUT) { o0[p + 1] = s1; o1[p + 1] = s3; }
    }
}

// ---------------------------------------------------------------------------
// Launch
// ---------------------------------------------------------------------------
extern "C" void kernel_launch(void* const* d_in, const int* in_sizes, int n_in,
                              void* d_out, int out_size)
{
    const float* x   = (const float*)d_in[0];
    const float* wm  = (const float*)d_in[1];
    const float* bm  = (const float*)d_in[2];
    const float* wr  = (const float*)d_in[3];
    const float* br  = (const float*)d_in[4];
    const float* wf  = (const float*)d_in[5];
    const float* bf  = (const float*)d_in[6];
    const float* wex = (const float*)d_in[7];
    const float* bex = (const float*)d_in[8];
    const float* wef = (const float*)d_in[9];
    const float* bef = (const float*)d_in[10];
    float* out = (float*)d_out;

    motif_kernel  <<<dim3(L / T1, B), TH1>>>(x, wm, bm, wr, br);
    fftconv_kernel<<<dim3(L / T3, B), TH3>>>(wf, bf);
    gate_kernel   <<<dim3(L / 1024, B), 256>>>(wex, bex);
    effect_kernel <<<dim3((LOUT + ET_POS - 1) / ET_POS, B), ET_TH>>>(wef, bef, out);
}

// round 10
// speedup vs baseline: 1.2808x; 1.2808x over previous
#include <cuda_runtime.h>
#include <math.h>
#include <stdint.h>

// ---------------------------------------------------------------------------
// Shapes (fixed by the problem)
// ---------------------------------------------------------------------------
#define B    32
#define L    65536
#define LOUT 64536          // L - 1000 (slice [500:-500])

// Scratch (device globals; allocation in kernel_launch is forbidden)
__device__ float g_y[(size_t)B * 40 * L];   // motif output (post-softplus)
__device__ float g_s[(size_t)B * 4 * L];    // reduce output
__device__ float g_t[(size_t)B * 4 * L];    // fftconv output
__device__ float g_m[(size_t)B * 40 * L];   // motifact (gated)

// ---------------------------------------------------------------------------
// tf32 MMA helpers (shared)
// ---------------------------------------------------------------------------
__device__ __forceinline__ uint32_t f2tf(float v) {
    uint32_t r;
    asm("cvt.rna.tf32.f32 %0, %1;" : "=r"(r) : "f"(v));
    return r;
}

__device__ __forceinline__ void mma_tf32(float& d0, float& d1, float& d2, float& d3,
                                         uint32_t a0, uint32_t a1, uint32_t a2, uint32_t a3,
                                         uint32_t b0, uint32_t b1) {
    asm volatile(
        "mma.sync.aligned.m16n8k8.row.col.f32.tf32.tf32.f32 "
        "{%0,%1,%2,%3}, {%4,%5,%6,%7}, {%8,%9}, {%0,%1,%2,%3};\n"
        : "+f"(d0), "+f"(d1), "+f"(d2), "+f"(d3)
        : "r"(a0), "r"(a1), "r"(a2), "r"(a3), "r"(b0), "r"(b1));
}

// ---------------------------------------------------------------------------
// Kernel 1: motif conv (4->40, K=51, pad 25) + softplus + reduce (40->4, 1x1)
//   (proven scalar version — frozen)
// ---------------------------------------------------------------------------
#define T1   512
#define TH1  128
#define K1P  52
#define XW1  564

__global__ __launch_bounds__(TH1)
void motif_kernel(const float* __restrict__ x,
                  const float* __restrict__ wm, const float* __restrict__ bm,
                  const float* __restrict__ wr, const float* __restrict__ br)
{
    __shared__ __align__(16) float swm[4 * K1P * 40];
    __shared__ float swr[4 * 40];
    __shared__ float sbm[40];
    __shared__ float sbr[4];
    __shared__ __align__(16) float sx[4 * XW1];

    const int b   = blockIdx.y;
    const int l0  = blockIdx.x * T1;
    const int tid = threadIdx.x;

    for (int i = tid; i < 4 * K1P * 40; i += TH1) {
        int c  = i / (K1P * 40);
        int r  = i - c * (K1P * 40);
        int k  = r / 40;
        int oc = r - k * 40;
        swm[i] = (k < 51) ? wm[(oc * 4 + c) * 51 + k] : 0.f;
    }
    for (int i = tid; i < 160; i += TH1) swr[i] = wr[i];
    if (tid < 40) sbm[tid] = bm[tid];
    if (tid < 4)  sbr[tid] = br[tid];

    for (int i = tid; i < 4 * XW1; i += TH1) {
        int c   = i / XW1;
        int off = i - c * XW1;
        int g   = l0 - 25 + off;
        sx[i]   = (g >= 0 && g < L) ? x[(b * 4 + c) * L + g] : 0.f;
    }
    __syncthreads();

    const int tp = tid * 4;

    float sacc[4][4];
#pragma unroll
    for (int rc = 0; rc < 4; rc++) {
        float bv = sbr[rc];
#pragma unroll
        for (int j = 0; j < 4; j++) sacc[rc][j] = bv;
    }

    for (int ocg = 0; ocg < 40; ocg += 8) {
        float acc[8][4];
#pragma unroll
        for (int o = 0; o < 8; o++) {
            float bv = sbm[ocg + o];
#pragma unroll
            for (int j = 0; j < 4; j++) acc[o][j] = bv;
        }

#pragma unroll
        for (int c = 0; c < 4; c++) {
            const float* xb = &sx[c * XW1 + tp];
            const float* wb = &swm[c * (K1P * 40) + ocg];
#pragma unroll 1
            for (int kg = 0; kg < K1P / 4; kg++) {
                const int k0 = kg * 4;
                float xq[8];
                float4 xa = *(const float4*)(xb + k0);
                float4 xc = *(const float4*)(xb + k0 + 4);
                xq[0]=xa.x; xq[1]=xa.y; xq[2]=xa.z; xq[3]=xa.w;
                xq[4]=xc.x; xq[5]=xc.y; xq[6]=xc.z; xq[7]=xc.w;
#pragma unroll
                for (int kk = 0; kk < 4; kk++) {
                    float4 wa = *(const float4*)(wb + (k0 + kk) * 40);
                    float4 wc = *(const float4*)(wb + (k0 + kk) * 40 + 4);
                    float wv[8] = {wa.x, wa.y, wa.z, wa.w, wc.x, wc.y, wc.z, wc.w};
#pragma unroll
                    for (int j = 0; j < 4; j++) {
                        float xv = xq[kk + j];
#pragma unroll
                        for (int o = 0; o < 8; o++)
                            acc[o][j] = fmaf(wv[o], xv, acc[o][j]);
                    }
                }
            }
        }

#pragma unroll
        for (int o = 0; o < 8; o++) {
            const int oc = ocg + o;
            float4 yv;
            float* yp = (float*)&yv;
#pragma unroll
            for (int j = 0; j < 4; j++) {
                float v  = acc[o][j];
                float sp = fmaxf(v, 0.f) + __logf(1.f + __expf(-fabsf(v)));
                yp[j] = sp;
#pragma unroll
                for (int rc = 0; rc < 4; rc++)
                    sacc[rc][j] = fmaf(swr[rc * 40 + oc], sp, sacc[rc][j]);
            }
            *(float4*)&g_y[(size_t)(b * 40 + oc) * L + l0 + tp] = yv;
        }
    }

#pragma unroll
    for (int rc = 0; rc < 4; rc++) {
        float4 sv = make_float4(sacc[rc][0], sacc[rc][1], sacc[rc][2], sacc[rc][3]);
        *(float4*)&g_s[(size_t)(b * 4 + rc) * L + l0 + tp] = sv;
    }
}

// ---------------------------------------------------------------------------
// Kernel 2: fftconv (4->4, K=401, pad 200) via tf32 mma, oc-packed banded GEMM
//
//   Tile = 32 positions. M = 16 rows = [oc(0..3) x 4 pos-groups of 8].
//   row = oc*4 + mp.  A[row][jj] = w_oc[jj - 8*mp]   (band, j in [0,432))
//   B[jj][n] = s_c[TO + n + jj - 200]                (Toeplitz)
//   A frag = 2 x LDS.64 (oc_lo / oc_hi arrays of {w[i], w[i+4]})
//   B frag = 1 x LDS.64 ({x[i], x[i+4]} window)
//   Warp: 8 tiles (256 pos). CTA: 4 warps = 1024 pos. Loop channels c=0..3.
// ---------------------------------------------------------------------------
#define FT_POS   1024       // positions per CTA
#define FT_TH    128
#define FT_NT    8          // 32-pos tiles per warp
#define FT_NJ    432        // extended j range (54 chunks of 8)
#define FT_WOFF  24         // band offset (max 8*mp shift)
#define FT_WPAD  464        // per-oc weight entries (uint2)
#define FT_XW    1472       // x window entries (uint2)

__global__ __launch_bounds__(FT_TH)
void fftconv_kernel(const float* __restrict__ wf, const float* __restrict__ bf)
{
    __shared__ __align__(16) uint2 sx[FT_XW];          // {tf32(s[i]), tf32(s[i+4])}
    __shared__ __align__(16) uint2 sw[4 * FT_WPAD];    // per-oc {w[k], w[k+4]}

    const int b    = blockIdx.y;
    const int TO0  = blockIdx.x * FT_POS;
    const int tid  = threadIdx.x;
    const int wid  = tid >> 5;
    const int lane = tid & 31;
    const int grp  = lane >> 2;                        // groupID 0..7
    const int tig  = lane & 3;                         // thread-in-group 0..3
    const int wrel = wid * (FT_NT * 32);               // warp base rel CTA

    const int oc_lo = grp >> 2;                        // rows g    -> oc 0/1
    const int oc_hi = oc_lo + 2;                       // rows g+8  -> oc 2/3
    const int mp    = grp & 3;

    // acc[t]: c0,c1 = oc_lo @ pos(8mp + 2tig, +1); c2,c3 = oc_hi same pos
    float acc[FT_NT][4];
    {
        float blo = bf[oc_lo], bhi = bf[oc_hi];
#pragma unroll
        for (int t = 0; t < FT_NT; t++) {
            acc[t][0] = blo; acc[t][1] = blo;
            acc[t][2] = bhi; acc[t][3] = bhi;
        }
    }

#pragma unroll 1
    for (int c = 0; c < 4; c++) {
        __syncthreads();   // protect previous channel's smem
        // weights: [oc][FT_WPAD] with band offset, oc-major, interleaved +4
        for (int i = tid; i < 4 * FT_WPAD; i += FT_TH) {
            int oc = i / FT_WPAD;
            int r  = i - oc * FT_WPAD;
            int k0 = r - FT_WOFF;
            int k1 = k0 + 4;
            float v0 = (k0 >= 0 && k0 < 401) ? wf[(oc * 4 + c) * 401 + k0] : 0.f;
            float v1 = (k1 >= 0 && k1 < 401) ? wf[(oc * 4 + c) * 401 + k1] : 0.f;
            sw[i] = make_uint2(f2tf(v0), f2tf(v1));
        }
        // x window: s index = TO0 - 200 + i
        {
            const float* sp = &g_s[(size_t)(b * 4 + c) * L];
            for (int i = tid; i < FT_XW; i += FT_TH) {
                int g  = TO0 - 200 + i;
                int g4 = g + 4;
                float v0 = (g  >= 0 && g  < L) ? sp[g]  : 0.f;
                float v1 = (g4 >= 0 && g4 < L) ? sp[g4] : 0.f;
                sx[i] = make_uint2(f2tf(v0), f2tf(v1));
            }
        }
        __syncthreads();

        const uint2* xw  = &sx[wrel];
        const uint2* wlo = &sw[oc_lo * FT_WPAD];
        const uint2* whi = &sw[oc_hi * FT_WPAD];
        int ai = FT_WOFF + tig - 8 * mp;    // + J0 each step
        int bi = grp + tig;                 // + J0 each step (+ t*32)
#pragma unroll 1
        for (int J0 = 0; J0 < FT_NJ; J0 += 8) {
            uint2 aLo = wlo[ai];            // (a0, a2)
            uint2 aHi = whi[ai];            // (a1, a3)
#pragma unroll
            for (int t = 0; t < FT_NT; t++) {
                uint2 bb = xw[bi + t * 32];
                mma_tf32(acc[t][0], acc[t][1], acc[t][2], acc[t][3],
                         aLo.x, aHi.x, aLo.y, aHi.y, bb.x, bb.y);
            }
            ai += 8; bi += 8;
        }
    }

    // epilogue: store to g_t (pos always in [0,L))
    float* tlo = &g_t[(size_t)(b * 4 + oc_lo) * L];
    float* thi = &g_t[(size_t)(b * 4 + oc_hi) * L];
#pragma unroll
    for (int t = 0; t < FT_NT; t++) {
        int pos = TO0 + wrel + t * 32 + 8 * mp + 2 * tig;
        *(float2*)&tlo[pos] = make_float2(acc[t][0], acc[t][1]);
        *(float2*)&thi[pos] = make_float2(acc[t][2], acc[t][3]);
    }
}

// ---------------------------------------------------------------------------
// Kernel 3: expand (4->40, 1x1) + sigmoid gate * y  -> motifact  (frozen)
// ---------------------------------------------------------------------------
__global__ __launch_bounds__(256)
void gate_kernel(const float* __restrict__ we, const float* __restrict__ be)
{
    __shared__ float sw[160];
    __shared__ float sb[40];
    const int tid = threadIdx.x;
    if (tid < 160) sw[tid] = we[tid];
    if (tid < 40)  sb[tid] = be[tid];
    __syncthreads();

    const int b = blockIdx.y;
    const int l = (blockIdx.x * 256 + tid) * 4;

    float4 tv[4];
#pragma unroll
    for (int rc = 0; rc < 4; rc++)
        tv[rc] = *(const float4*)&g_t[(size_t)(b * 4 + rc) * L + l];

    for (int oc = 0; oc < 40; oc++) {
        float w0 = sw[oc * 4 + 0], w1 = sw[oc * 4 + 1];
        float w2 = sw[oc * 4 + 2], w3 = sw[oc * 4 + 3];
        float bb = sb[oc];
        float4 g;
        g.x = bb + w0 * tv[0].x + w1 * tv[1].x + w2 * tv[2].x + w3 * tv[3].x;
        g.y = bb + w0 * tv[0].y + w1 * tv[1].y + w2 * tv[2].y + w3 * tv[3].y;
        g.z = bb + w0 * tv[0].z + w1 * tv[1].z + w2 * tv[2].z + w3 * tv[3].z;
        g.w = bb + w0 * tv[0].w + w1 * tv[1].w + w2 * tv[2].w + w3 * tv[3].w;
        g.x = 1.f / (1.f + __expf(-g.x));
        g.y = 1.f / (1.f + __expf(-g.y));
        g.z = 1.f / (1.f + __expf(-g.z));
        g.w = 1.f / (1.f + __expf(-g.w));
        size_t idx = (size_t)(b * 40 + oc) * L + l;
        float4 yv = *(const float4*)&g_y[idx];
        float4 mv = make_float4(g.x * yv.x, g.y * yv.y, g.z * yv.z, g.w * yv.w);
        *(float4*)&g_m[idx] = mv;
    }
}

// ---------------------------------------------------------------------------
// Kernel 4: effect conv (40->2, K=601) via tf32 mma.sync — R8 proven version.
// ---------------------------------------------------------------------------
#define ET_POS   2048       // positions per CTA
#define ET_TH    128
#define ET_WLEN  2656       // smem window per channel
#define ET_WPAD  864        // padded weight array per (oc, cc)
#define ET_CH    2          // channels per chunk
#define ET_NJ    728        // extended j range (91 chunks of 8)

__global__ __launch_bounds__(ET_TH)
void effect_kernel(const float* __restrict__ w, const float* __restrict__ bias,
                   float* __restrict__ out)
{
    __shared__ uint32_t sm_x[ET_CH * ET_WLEN];     // tf32 bits of x window
    __shared__ uint32_t sm_w[2 * ET_CH * ET_WPAD]; // tf32 bits, [oc][cc][WPAD]

    const int b    = blockIdx.y;
    const int LOc  = blockIdx.x * ET_POS;
    const int tid  = threadIdx.x;
    const int wid  = tid >> 5;
    const int lane = tid & 31;
    const int grp  = lane >> 2;
    const int tig  = lane & 3;
    const int wrel = wid * 512;

    float acc[4][2][4];
    const float b0v = bias[0], b1v = bias[1];
#pragma unroll
    for (int t = 0; t < 4; t++)
#pragma unroll
        for (int r = 0; r < 4; r++) { acc[t][0][r] = b0v; acc[t][1][r] = b1v; }

    for (int ch0 = 0; ch0 < 40; ch0 += ET_CH) {
        __syncthreads();
        for (int i = tid; i < 2 * ET_CH * ET_WPAD; i += ET_TH) sm_w[i] = 0u;
        __syncthreads();
        for (int i = tid; i < 2 * ET_CH * 601; i += ET_TH) {
            int oc = i / (ET_CH * 601);
            int r  = i - oc * (ET_CH * 601);
            int cc = r / 601;
            int k  = r - cc * 601;
            sm_w[(oc * ET_CH + cc) * ET_WPAD + 128 + k] =
                f2tf(w[((size_t)(oc * 40 + ch0 + cc)) * 601 + k]);
        }
        for (int i = tid; i < ET_CH * ET_WLEN; i += ET_TH) {
            int cc  = i / ET_WLEN;
            int off = i - cc * ET_WLEN;
            int g   = LOc + 200 + off;
            float v = (g < L) ? g_m[(size_t)(b * 40 + ch0 + cc) * L + g] : 0.f;
            sm_x[i] = f2tf(v);
        }
        __syncthreads();

#pragma unroll 1
        for (int cc = 0; cc < ET_CH; cc++) {
            const uint32_t* xw  = &sm_x[cc * ET_WLEN + wrel];
            const uint32_t* w0p = &sm_w[(0 * ET_CH + cc) * ET_WPAD];
            const uint32_t* w1p = &sm_w[(1 * ET_CH + cc) * ET_WPAD];
            int ai = 128 + tig - 8 * grp;
            int bi = grp + tig;
#pragma unroll 1
            for (int J0 = 0; J0 < ET_NJ; J0 += 8) {
                uint32_t a00 = w0p[ai],     a01 = w0p[ai - 64];
                uint32_t a02 = w0p[ai + 4], a03 = w0p[ai - 60];
                uint32_t a10 = w1p[ai],     a11 = w1p[ai - 64];
                uint32_t a12 = w1p[ai + 4], a13 = w1p[ai - 60];
#pragma unroll
                for (int t = 0; t < 4; t++) {
                    uint32_t bb0 = xw[bi + t * 128];
                    uint32_t bb1 = xw[bi + t * 128 + 4];
                    mma_tf32(acc[t][0][0], acc[t][0][1], acc[t][0][2], acc[t][0][3],
                             a00, a01, a02, a03, bb0, bb1);
                    mma_tf32(acc[t][1][0], acc[t][1][1], acc[t][1][2], acc[t][1][3],
                             a10, a11, a12, a13, bb0, bb1);
                }
                ai += 8; bi += 8;
            }
        }
    }

#pragma unroll
    for (int t = 0; t < 4; t++) {
        int base = LOc + wrel + t * 128;
        int p0   = base + 8 * grp + 2 * tig;
        int p2   = p0 + 64;
#pragma unroll
        for (int oc = 0; oc < 2; oc++) {
            float* op = out + (size_t)(b * 2 + oc) * LOUT;
            float s0 = 1.f / (1.f + __expf(-acc[t][oc][0]));
            float s1 = 1.f / (1.f + __expf(-acc[t][oc][1]));
            float s2 = 1.f / (1.f + __expf(-acc[t][oc][2]));
            float s3 = 1.f / (1.f + __expf(-acc[t][oc][3]));
            if (p0 < LOUT)     op[p0]     = s0;
            if (p0 + 1 < LOUT) op[p0 + 1] = s1;
            if (p2 < LOUT)     op[p2]     = s2;
            if (p2 + 1 < LOUT) op[p2 + 1] = s3;
        }
    }
}

// ---------------------------------------------------------------------------
// Launch
// ---------------------------------------------------------------------------
extern "C" void kernel_launch(void* const* d_in, const int* in_sizes, int n_in,
                              void* d_out, int out_size)
{
    const float* x   = (const float*)d_in[0];
    const float* wm  = (const float*)d_in[1];
    const float* bm  = (const float*)d_in[2];
    const float* wr  = (const float*)d_in[3];
    const float* br  = (const float*)d_in[4];
    const float* wf  = (const float*)d_in[5];
    const float* bf  = (const float*)d_in[6];
    const float* wex = (const float*)d_in[7];
    const float* bex = (const float*)d_in[8];
    const float* wef = (const float*)d_in[9];
    const float* bef = (const float*)d_in[10];
    float* out = (float*)d_out;

    motif_kernel  <<<dim3(L / T1, B), TH1>>>(x, wm, bm, wr, br);
    fftconv_kernel<<<dim3(L / FT_POS, B), FT_TH>>>(wf, bf);
    gate_kernel   <<<dim3(L / 1024, B), 256>>>(wex, bex);
    effect_kernel <<<dim3((LOUT + ET_POS - 1) / ET_POS, B), ET_TH>>>(wef, bef, out);
}